// round 10
// baseline (speedup 1.0000x reference)
#include <cuda_runtime.h>
#include <cstdint>

// CASSI forward: single-launch TMA pipeline, half-row blocks, halo seeding,
// split-j reduce (256 threads).
//
// Grid (2, 1024): block (h, m) computes y[m, c] for c in [h*512, ...).
//  h=0: c in [0, 512);  h=1: c in [512, 1087) - seeds its diagonal carry
//  from a 63-row halo tile (n in [449,512), 16KB TMA, L2-resident since h=0
//  reads the same rows). No atomics, no zero-init, one launch.
// Per tile (TN=128 n-rows, 32KB, 2-deep TMA ring): 64 diagonal terms split
// j<32 (group A) / j>=32 (group B); B's partials combine via smem.

#define MM    1024
#define NN    1024
#define LL    64
#define OUTC  (NN + LL - 1)           // 1087
#define TN    128
#define TPB   256
#define HALF  512
#define NTIL  (HALF / TN)             // 4
#define TILE_BYTES (TN * LL * 4)      // 32768
#define HALO_ROWS  (LL - 1)           // 63
#define HALO_BYTES (HALO_ROWS * LL * 4)  // 16128

__device__ __forceinline__ uint32_t smem_u32(const void* p)
{
    uint32_t a;
    asm("{ .reg .u64 t; cvta.to.shared.u64 t, %1; cvt.u32.u64 %0, t; }"
        : "=r"(a) : "l"(p));
    return a;
}

__device__ __forceinline__ void mbar_init(uint32_t mb, uint32_t count)
{
    asm volatile("mbarrier.init.shared.b64 [%0], %1;" :: "r"(mb), "r"(count) : "memory");
}

__device__ __forceinline__ void tma_bulk(uint32_t dst, const float* src,
                                         uint32_t bytes, uint32_t mb)
{
    asm volatile("mbarrier.arrive.expect_tx.shared.b64 _, [%0], %1;"
                 :: "r"(mb), "r"(bytes) : "memory");
    asm volatile("cp.async.bulk.shared::cta.global.mbarrier::complete_tx::bytes "
                 "[%0], [%1], %2, [%3];"
                 :: "r"(dst), "l"(src), "r"(bytes), "r"(mb) : "memory");
}

__device__ __forceinline__ void mbar_wait(uint32_t mb, uint32_t parity)
{
    uint32_t done;
    asm volatile(
        "{\n\t"
        ".reg .pred p;\n\t"
        "mbarrier.try_wait.parity.acquire.cta.shared::cta.b64 p, [%1], %2;\n\t"
        "selp.b32 %0, 1, 0, p;\n\t"
        "}"
        : "=r"(done) : "r"(mb), "r"(parity) : "memory");
    if (!done) {
        asm volatile(
            "{\n\t"
            ".reg .pred P1;\n\t"
            "W%=:\n\t"
            "mbarrier.try_wait.parity.acquire.cta.shared::cta.b64 P1, [%0], %1;\n\t"
            "@P1 bra D%=;\n\t"
            "bra W%=;\n\t"
            "D%=:\n\t"
            "}"
            :: "r"(mb), "r"(parity) : "memory");
    }
}

__global__ __launch_bounds__(TPB)
void cassi_halo_kernel(const float* __restrict__ x,
                       const float* __restrict__ ca,
                       float* __restrict__ y)
{
    extern __shared__ float smem[];
    float* buf0 = smem;                          // 8192 floats (32KB)
    float* buf1 = buf0 + TN * LL;                // 8192 floats (32KB)
    float* halo = buf1 + TN * LL;                // 4032 floats (16128B)
    float* sca  = halo + HALO_ROWS * LL;         // 512 floats
    float* scah = sca + HALF;                    // 63 floats (pad 64)
    float* spL  = scah + 64;                     // 2*128 floats
    float* spH  = spL + 2 * 128;                 // 2*128 floats
    __shared__ __align__(8) uint64_t mbar_store[3];

    const int m    = blockIdx.y;
    const int h    = blockIdx.x;                 // 0 or 1
    const int n0   = h * HALF;
    const int tid  = threadIdx.x;
    const int half = tid >> 7;                   // j-group: 0 -> j<32, 1 -> j>=32
    const int lane = tid & 127;                  // output lane within tile

    const float* xbase = x + (size_t)m * (NN * LL);
    const float* xrow  = xbase + (size_t)n0 * LL;
    float*       yrow  = y + (size_t)m * OUTC;

    const uint32_t mb0 = smem_u32(&mbar_store[0]);
    const uint32_t mb1 = smem_u32(&mbar_store[1]);
    const uint32_t mb2 = smem_u32(&mbar_store[2]);
    const uint32_t b0  = smem_u32(buf0);
    const uint32_t b1  = smem_u32(buf1);

    if (tid == 0) {
        mbar_init(mb0, 1);
        mbar_init(mb1, 1);
        mbar_init(mb2, 1);
    }
    __syncthreads();

    if (tid == 0) {
        tma_bulk(b0, xrow,           TILE_BYTES, mb0);
        tma_bulk(b1, xrow + TN * LL, TILE_BYTES, mb1);
        if (h == 1)
            tma_bulk(smem_u32(halo), xbase + (size_t)(n0 - HALO_ROWS) * LL,
                     HALO_BYTES, mb2);
    }

    // Stage ca for this half (+ halo ca for h=1).
    #pragma unroll
    for (int i = tid; i < HALF; i += TPB)
        sca[i] = ca[m * NN + n0 + i];
    if (h == 1 && tid < HALO_ROWS)
        scah[tid] = ca[m * NN + (n0 - HALO_ROWS) + tid];
    __syncthreads();

    // Seed carry. h=1: from halo tile.
    //   carry[lane] = sum_{k=lane}^{62} halo[k][63+lane-k] * scah[k]
    float carry = 0.0f;
    if (h == 1) {
        mbar_wait(mb2, 0);
        if (half == 0 && lane < HALO_ROWS) {
            #pragma unroll
            for (int k = 0; k < HALO_ROWS; ++k) {
                if (k >= lane)
                    carry = fmaf(halo[k * LL + (HALO_ROWS + lane - k)], scah[k], carry);
            }
        }
    }

    #pragma unroll 1
    for (int t = 0; t < NTIL; ++t) {
        const uint32_t mb     = (t & 1) ? mb1 : mb0;
        const float*   cur    = (t & 1) ? buf1 : buf0;
        const uint32_t parity = (t >> 1) & 1;

        mbar_wait(mb, parity);

        const float* scat  = sca + t * TN;
        const int    jbase = half * 32;
        float pL = 0.0f, pH = 0.0f;
        #pragma unroll
        for (int jj = 0; jj < 32; ++jj) {
            const int  l   = (lane + jbase + jj) & (LL - 1);
            const bool low = (l <= lane);
            const int  n   = low ? (lane - l) : (lane + TN - l);
            const float v  = cur[n * LL + l];
            if (low) pL = fmaf(v, scat[n], pL);
            else     pH = fmaf(v, scat[n], pH);
        }
        if (half == 1) {
            spL[(t & 1) * 128 + lane] = pL;
            spH[(t & 1) * 128 + lane] = pH;
        }
        __syncthreads();    // all reads of `cur` done; B partials visible

        if (tid == 0 && t + 2 < NTIL) {
            const uint32_t db = (t & 1) ? b1 : b0;
            tma_bulk(db, xrow + (size_t)(t + 2) * TN * LL, TILE_BYTES, mb);
        }
        if (half == 0) {
            const float accL = carry + pL + spL[(t & 1) * 128 + lane];
            carry            = pH + spH[(t & 1) * 128 + lane];
            yrow[n0 + t * TN + lane] = accL;
        }
        // partial arrays are double-buffered on t&1 -> no second sync needed
    }

    // Tail: h=1 writes c in [NN, NN+LL-1) from its final carry; h=0 discards
    // (those columns are fully computed by h=1 via the halo).
    if (h == 1 && half == 0 && lane < LL - 1)
        yrow[NN + lane] = carry;
}

extern "C" void kernel_launch(void* const* d_in, const int* in_sizes, int n_in,
                              void* d_out, int out_size)
{
    const float* x  = (const float*)d_in[0];
    const float* ca = (const float*)d_in[1];
    float* y        = (float*)d_out;

    const int smem_bytes =
        (2 * TN * LL + HALO_ROWS * LL + HALF + 64 + 4 * 128) * sizeof(float);

    cudaFuncSetAttribute(cassi_halo_kernel,
                         cudaFuncAttributeMaxDynamicSharedMemorySize,
                         smem_bytes);

    cassi_halo_kernel<<<dim3(2, MM), TPB, smem_bytes>>>(x, ca, y);
}